// round 14
// baseline (speedup 1.0000x reference)
#include <cuda_runtime.h>
#include <cuda_bf16.h>
#include <math.h>
#include <stdint.h>

#define TT 4096   // tokens
#define DD 1024   // d_model
#define FF 4096   // d_ff
#define EE 8      // experts
#define SLOTS (TT*2)

// ======================= helpers =======================
__device__ __forceinline__ void mma_bf16(float* c, const uint32_t* a, uint32_t b0, uint32_t b1) {
    asm volatile("mma.sync.aligned.m16n8k16.row.col.f32.bf16.bf16.f32 "
        "{%0,%1,%2,%3}, {%4,%5,%6,%7}, {%8,%9}, {%0,%1,%2,%3};"
        : "+f"(c[0]), "+f"(c[1]), "+f"(c[2]), "+f"(c[3])
        : "r"(a[0]), "r"(a[1]), "r"(a[2]), "r"(a[3]), "r"(b0), "r"(b1));
}

// ======================= scratch =======================
// fp32 fallback buffers
__device__ float g_hid[(size_t)SLOTS * FF];
__device__ float g_hid_s[(size_t)TT * FF];
// bf16 split buffers (HMMA path)
__device__ __align__(256) __nv_bfloat16 g_h_hi[(size_t)TT * DD];
__device__ __align__(256) __nv_bfloat16 g_h_lo[(size_t)TT * DD];
__device__ __align__(256) __nv_bfloat16 g_We1t_hi[(size_t)EE * FF * DD];
__device__ __align__(256) __nv_bfloat16 g_We1t_lo[(size_t)EE * FF * DD];
__device__ __align__(256) __nv_bfloat16 g_We2t_hi[(size_t)EE * DD * FF];
__device__ __align__(256) __nv_bfloat16 g_We2t_lo[(size_t)EE * DD * FF];
__device__ __align__(256) __nv_bfloat16 g_Ws1t_hi[(size_t)FF * DD];
__device__ __align__(256) __nv_bfloat16 g_Ws1t_lo[(size_t)FF * DD];
__device__ __align__(256) __nv_bfloat16 g_Ws2t_hi[(size_t)DD * FF];
__device__ __align__(256) __nv_bfloat16 g_Ws2t_lo[(size_t)DD * FF];
__device__ __align__(256) __nv_bfloat16 g_hid_hi[(size_t)SLOTS * FF];
__device__ __align__(256) __nv_bfloat16 g_hid_lo[(size_t)SLOTS * FF];
__device__ __align__(256) __nv_bfloat16 g_hs_hi[(size_t)TT * FF];
__device__ __align__(256) __nv_bfloat16 g_hs_lo[(size_t)TT * FF];
__device__ __align__(256) float g_partial[(size_t)SLOTS * DD];   // shared by both paths (stream-ordered)
// routing
__device__ int   g_perm[SLOTS];
__device__ float g_wgt[SLOTS];
__device__ int   g_posmap[SLOTS];
__device__ int   g_tok_e[SLOTS];
__device__ float g_tok_w[SLOTS];
__device__ int   g_counts[EE];
__device__ int   g_offsets[EE];
__device__ int   g_cursor[EE];
__device__ int   g_fail;

__device__ __forceinline__ float gelu_tanh(float x) {
    float x3 = x * x * x;
    float t = tanhf(0.7978845608028654f * (x + 0.044715f * x3));
    return 0.5f * x * (1.0f + t);
}
__device__ __forceinline__ void split_bf16(float v, __nv_bfloat16& hi, __nv_bfloat16& lo) {
    hi = __float2bfloat16(v);
    lo = __float2bfloat16(v - __bfloat162float(hi));
}

// ======================= small kernels =======================
__global__ void init_kernel(float* out, int out_size) {
    if (threadIdx.x < EE) g_counts[threadIdx.x] = 0;
    if (threadIdx.x == 0) {
        g_fail = 0;
        if (out_size > TT * DD) out[TT * DD] = 0.125f;   // mean softmax = 1/E exactly
    }
}

__global__ void router_kernel(const float* __restrict__ h,
                              const float* __restrict__ Wr,
                              const float* __restrict__ br) {
    int warp = (blockIdx.x * blockDim.x + threadIdx.x) >> 5;
    int lane = threadIdx.x & 31;
    if (warp >= TT) return;
    const float* hrow = h + (size_t)warp * DD;
    float s[EE];
#pragma unroll
    for (int e = 0; e < EE; e++) s[e] = 0.f;
    for (int d = lane; d < DD; d += 32) {
        float hv = hrow[d];
        const float4* w4 = (const float4*)(Wr + (size_t)d * EE);
        float4 a = w4[0], b = w4[1];
        s[0] += hv * a.x; s[1] += hv * a.y; s[2] += hv * a.z; s[3] += hv * a.w;
        s[4] += hv * b.x; s[5] += hv * b.y; s[6] += hv * b.z; s[7] += hv * b.w;
    }
#pragma unroll
    for (int e = 0; e < EE; e++)
#pragma unroll
        for (int o = 16; o > 0; o >>= 1) s[e] += __shfl_down_sync(0xffffffffu, s[e], o);
    if (lane == 0) {
        float l[EE];
#pragma unroll
        for (int e = 0; e < EE; e++) l[e] = s[e] + br[e];
        float m = l[0];
#pragma unroll
        for (int e = 1; e < EE; e++) m = fmaxf(m, l[e]);
        float p[EE], sum = 0.f;
#pragma unroll
        for (int e = 0; e < EE; e++) { p[e] = expf(l[e] - m); sum += p[e]; }
        int i0 = 0;
#pragma unroll
        for (int e = 1; e < EE; e++) if (l[e] > l[i0]) i0 = e;
        int i1 = -1;
#pragma unroll
        for (int e = 0; e < EE; e++) {
            if (e == i0) continue;
            if (i1 < 0 || l[e] > l[i1]) i1 = e;
        }
        float inv = 1.f / sum;
        g_tok_e[warp * 2 + 0] = i0; g_tok_w[warp * 2 + 0] = p[i0] * inv;
        g_tok_e[warp * 2 + 1] = i1; g_tok_w[warp * 2 + 1] = p[i1] * inv;
        atomicAdd(&g_counts[i0], 1);
        atomicAdd(&g_counts[i1], 1);
    }
}

__global__ void scan_kernel() {
    if (threadIdx.x == 0) {
        int acc = 0;
        for (int e = 0; e < EE; e++) { g_offsets[e] = acc; g_cursor[e] = acc; acc += g_counts[e]; }
    }
}

__global__ void scatter_kernel() {
    int t = blockIdx.x * blockDim.x + threadIdx.x;
    if (t >= TT) return;
#pragma unroll
    for (int k = 0; k < 2; k++) {
        int e = g_tok_e[t * 2 + k];
        int pos = atomicAdd(&g_cursor[e], 1);
        g_perm[pos] = t;
        g_wgt[pos] = g_tok_w[t * 2 + k];
        g_posmap[t * 2 + k] = pos;
    }
}

__global__ void conv_h_kernel(const float* __restrict__ h) {
    int i4 = blockIdx.x * blockDim.x + threadIdx.x;
    if (i4 >= TT * DD / 4) return;
    float4 v = ((const float4*)h)[i4];
    __nv_bfloat16 hh[4], ll[4];
    split_bf16(v.x, hh[0], ll[0]); split_bf16(v.y, hh[1], ll[1]);
    split_bf16(v.z, hh[2], ll[2]); split_bf16(v.w, hh[3], ll[3]);
    ((uint2*)g_h_hi)[i4] = *(uint2*)hh;
    ((uint2*)g_h_lo)[i4] = *(uint2*)ll;
}

__global__ void transpose_split(const float* __restrict__ W,
                                __nv_bfloat16* __restrict__ Oh,
                                __nv_bfloat16* __restrict__ Ol,
                                int K, int N) {
    __shared__ float s[32][33];
    int e = blockIdx.z;
    W  += (size_t)e * K * N;
    Oh += (size_t)e * N * K;
    Ol += (size_t)e * N * K;
    int k0 = blockIdx.x * 32, n0 = blockIdx.y * 32;
    int tx = threadIdx.x, ty = threadIdx.y;  // 32 x 8
#pragma unroll
    for (int i = 0; i < 4; i++)
        s[ty + i * 8][tx] = W[(size_t)(k0 + ty + i * 8) * N + n0 + tx];
    __syncthreads();
#pragma unroll
    for (int i = 0; i < 4; i++) {
        int n = n0 + ty + i * 8, k = k0 + tx;
        float v = s[tx][ty + i * 8];
        __nv_bfloat16 hi, lo;
        split_bf16(v, hi, lo);
        Oh[(size_t)n * K + k] = hi;
        Ol[(size_t)n * K + k] = lo;
    }
}

// ======================= HMMA GEMM: plain LDG/STS, mma.sync only exotic op =======================
// 128x128 CTA tile, 8 warps (2 x 4), 64x32 warp tile, KC=16.
// Tiles Ahi/Alo/Bhi/Blo: [128 rows x 32 B], 16B-chunk XOR swizzle (conflict-free
// for both STS and the per-fragment 32-bit LDS).
// Single smem stage (16 KB) + register prefetch of the next chunk.
#define KC 16
#define TILE_B 4096
#define STAGE_B (4 * TILE_B)
#define SWZ(row, kb) ((row) * 32 + (((((kb) >> 4) ^ (((row) >> 2) & 1))) << 4) + ((kb) & 15))

template <int MODE>
__global__ void __launch_bounds__(256)
gemm_mm(const float* __restrict__ bias, float* __restrict__ dout) {
    const int Ktot = (MODE == 0 || MODE == 2) ? DD : FF;
    const int CH = Ktot / KC;
    const int e = blockIdx.z;
    const int n0 = blockIdx.x * 128;
    const int m0 = blockIdx.y * 128;

    int cnt = 0, base = 0;
    if (MODE <= 1) {
        cnt = g_counts[e];
        base = g_offsets[e];
        if (m0 >= cnt) return;
    }

    __shared__ __align__(16) char sm[STAGE_B];           // 16 KB
    __shared__ const __nv_bfloat16* ApH[128];
    __shared__ const __nv_bfloat16* ApL[128];

    const int tid = threadIdx.x, wid = tid >> 5, lane = tid & 31;

    const __nv_bfloat16 *Bhi, *Blo;
    const float* bvec;
    if (MODE == 0)      { Bhi = g_We1t_hi + (size_t)e * FF * DD; Blo = g_We1t_lo + (size_t)e * FF * DD; bvec = bias + (size_t)e * FF; }
    else if (MODE == 1) { Bhi = g_We2t_hi + (size_t)e * DD * FF; Blo = g_We2t_lo + (size_t)e * DD * FF; bvec = bias + (size_t)e * DD; }
    else if (MODE == 2) { Bhi = g_Ws1t_hi; Blo = g_Ws1t_lo; bvec = bias; }
    else                { Bhi = g_Ws2t_hi; Blo = g_Ws2t_lo; bvec = bias; }

    for (int r = tid; r < 128; r += 256) {
        int mr = m0 + r;
        const __nv_bfloat16 *ph, *pl;
        if (MODE == 0) {
            int mm = (mr < cnt) ? mr : (cnt - 1);
            int t = g_perm[base + mm];
            ph = g_h_hi + (size_t)t * DD; pl = g_h_lo + (size_t)t * DD;
        } else if (MODE == 1) {
            int mm = (mr < cnt) ? mr : (cnt - 1);
            ph = g_hid_hi + (size_t)(base + mm) * FF; pl = g_hid_lo + (size_t)(base + mm) * FF;
        } else if (MODE == 2) {
            ph = g_h_hi + (size_t)mr * DD; pl = g_h_lo + (size_t)mr * DD;
        } else {
            ph = g_hs_hi + (size_t)mr * FF; pl = g_hs_lo + (size_t)mr * FF;
        }
        ApH[r] = ph; ApL[r] = pl;
    }
    __syncthreads();

    // per-thread slice of the chunk: 4 x 16B (tile, row, chunk fixed per i)
    int ti[4], rr[4], cc[4];
#pragma unroll
    for (int i = 0; i < 4; i++) {
        int u = tid + i * 256;
        ti[i] = u >> 8;
        int w = u & 255;
        rr[i] = w >> 1; cc[i] = w & 1;
    }

    auto fetch = [&](int c, uint4* v) {
        const int k0 = c * KC;
#pragma unroll
        for (int i = 0; i < 4; i++) {
            const __nv_bfloat16* src;
            if (ti[i] == 0)      src = ApH[rr[i]] + k0 + cc[i] * 8;
            else if (ti[i] == 1) src = ApL[rr[i]] + k0 + cc[i] * 8;
            else if (ti[i] == 2) src = Bhi + (size_t)(n0 + rr[i]) * Ktot + k0 + cc[i] * 8;
            else                 src = Blo + (size_t)(n0 + rr[i]) * Ktot + k0 + cc[i] * 8;
            v[i] = *(const uint4*)src;
        }
    };
    auto store_sm = [&](const uint4* v) {
#pragma unroll
        for (int i = 0; i < 4; i++)
            *(uint4*)(sm + ti[i] * TILE_B + rr[i] * 32 + ((cc[i] ^ ((rr[i] >> 2) & 1)) << 4)) = v[i];
    };

    const int wm = wid & 1, wn = wid >> 1;
    const int gid = lane >> 2, t2 = lane & 3;

    float acc[4][4][4];
#pragma unroll
    for (int i = 0; i < 4; i++)
#pragma unroll
        for (int j = 0; j < 4; j++)
#pragma unroll
            for (int q = 0; q < 4; q++) acc[i][j][q] = 0.f;

    uint4 cur[4], nxt[4];
    fetch(0, cur);

    for (int c = 0; c < CH; c++) {
        store_sm(cur);
        __syncthreads();
        if (c + 1 < CH) fetch(c + 1, nxt);   // LDG latency hidden under compute

        const char* tAH = sm;
        const char* tAL = sm + TILE_B;
        const char* tBH = sm + 2 * TILE_B;
        const char* tBL = sm + 3 * TILE_B;
        const int kb0 = t2 * 4, kb1 = t2 * 4 + 16;

        uint32_t ahi[4][4], alo[4][4], bh0[4], bh1[4], bl0[4], bl1[4];
#pragma unroll
        for (int im = 0; im < 4; im++) {
            const int r0 = wm * 64 + im * 16 + gid;
            const int r1 = r0 + 8;
            ahi[im][0] = *(const uint32_t*)(tAH + SWZ(r0, kb0));
            ahi[im][1] = *(const uint32_t*)(tAH + SWZ(r1, kb0));
            ahi[im][2] = *(const uint32_t*)(tAH + SWZ(r0, kb1));
            ahi[im][3] = *(const uint32_t*)(tAH + SWZ(r1, kb1));
            alo[im][0] = *(const uint32_t*)(tAL + SWZ(r0, kb0));
            alo[im][1] = *(const uint32_t*)(tAL + SWZ(r1, kb0));
            alo[im][2] = *(const uint32_t*)(tAL + SWZ(r0, kb1));
            alo[im][3] = *(const uint32_t*)(tAL + SWZ(r1, kb1));
        }
#pragma unroll
        for (int nb = 0; nb < 4; nb++) {
            const int n = wn * 32 + nb * 8 + gid;
            bh0[nb] = *(const uint32_t*)(tBH + SWZ(n, kb0));
            bh1[nb] = *(const uint32_t*)(tBH + SWZ(n, kb1));
            bl0[nb] = *(const uint32_t*)(tBL + SWZ(n, kb0));
            bl1[nb] = *(const uint32_t*)(tBL + SWZ(n, kb1));
        }
#pragma unroll
        for (int im = 0; im < 4; im++)
#pragma unroll
            for (int nb = 0; nb < 4; nb++) {
                mma_bf16(acc[im][nb], ahi[im], bh0[nb], bh1[nb]);
                mma_bf16(acc[im][nb], ahi[im], bl0[nb], bl1[nb]);
                mma_bf16(acc[im][nb], alo[im], bh0[nb], bh1[nb]);
            }
        __syncthreads();
#pragma unroll
        for (int i = 0; i < 4; i++) cur[i] = nxt[i];
    }

    // ---------------- epilogue ----------------
#pragma unroll
    for (int im = 0; im < 4; im++) {
        const int tr = wm * 64 + im * 16 + gid;
#pragma unroll
        for (int half = 0; half < 2; half++) {
            const int row = tr + half * 8;
            const int mr = m0 + row;
            if (MODE <= 1 && mr >= cnt) continue;
#pragma unroll
            for (int nb = 0; nb < 4; nb++) {
                const int col = n0 + wn * 32 + nb * 8 + t2 * 2;
                float v0 = acc[im][nb][half * 2 + 0] + bvec[col];
                float v1 = acc[im][nb][half * 2 + 1] + bvec[col + 1];
                if (MODE == 0 || MODE == 2) {
                    v0 = gelu_tanh(v0); v1 = gelu_tanh(v1);
                    __nv_bfloat16 h0, l0, h1, l1;
                    split_bf16(v0, h0, l0); split_bf16(v1, h1, l1);
                    uint32_t ph = (uint32_t)__bfloat16_as_ushort(h0) | ((uint32_t)__bfloat16_as_ushort(h1) << 16);
                    uint32_t pl = (uint32_t)__bfloat16_as_ushort(l0) | ((uint32_t)__bfloat16_as_ushort(l1) << 16);
                    size_t rowoff = (MODE == 0) ? (size_t)(base + mr) * FF : (size_t)mr * FF;
                    __nv_bfloat16* dh = (MODE == 0 ? g_hid_hi : g_hs_hi) + rowoff + col;
                    __nv_bfloat16* dl = (MODE == 0 ? g_hid_lo : g_hs_lo) + rowoff + col;
                    *(uint32_t*)dh = ph;
                    *(uint32_t*)dl = pl;
                } else if (MODE == 1) {
                    float w = g_wgt[base + mr];
                    float2* dst = (float2*)(g_partial + (size_t)(base + mr) * DD + col);
                    *dst = make_float2(w * v0, w * v1);
                } else {
                    int p0 = g_posmap[2 * mr], p1 = g_posmap[2 * mr + 1];
                    const float2 r0 = *(const float2*)(g_partial + (size_t)p0 * DD + col);
                    const float2 r1 = *(const float2*)(g_partial + (size_t)p1 * DD + col);
                    float2* dst = (float2*)(dout + (size_t)mr * DD + col);
                    *dst = make_float2(v0 + r0.x + r1.x, v1 + r0.y + r1.y);
                }
            }
        }
    }
}

// ======================= checker: sample-verify all 4 HMMA stages =======================
__global__ void check_kernel(const float* __restrict__ h,
                             const float* __restrict__ We1, const float* __restrict__ be1,
                             const float* __restrict__ We2, const float* __restrict__ be2,
                             const float* __restrict__ Ws1, const float* __restrict__ bs1,
                             const float* __restrict__ Ws2, const float* __restrict__ bs2,
                             const float* __restrict__ out) {
    int gwarp = (blockIdx.x * blockDim.x + threadIdx.x) >> 5;   // 0..511
    int lane = threadIdx.x & 31;
    int stage = gwarp & 3, s = gwarp >> 2;                      // 128 samples/stage

    float ref = 0.f, got = 0.f, acc = 0.f;
    if (stage == 0) {                    // expert GEMM1: g_hid_hi/lo
        int slot = (s * 977 + 13) % SLOTS;
        int e = 0;
        for (int q = 0; q < EE; q++)
            if (slot >= g_offsets[q] && slot < g_offsets[q] + g_counts[q]) e = q;
        int tok = g_perm[slot];
        int n = (s * 613 + 17) % FF;
        for (int k = lane; k < DD; k += 32)
            acc += h[(size_t)tok * DD + k] * We1[(size_t)e * DD * FF + (size_t)k * FF + n];
        for (int o = 16; o > 0; o >>= 1) acc += __shfl_down_sync(0xffffffffu, acc, o);
        ref = gelu_tanh(acc + be1[(size_t)e * FF + n]);
        got = __bfloat162float(g_hid_hi[(size_t)slot * FF + n]) +
              __bfloat162float(g_hid_lo[(size_t)slot * FF + n]);
    } else if (stage == 1) {             // expert GEMM2: g_partial
        int slot = (s * 769 + 7) % SLOTS;
        int e = 0;
        for (int q = 0; q < EE; q++)
            if (slot >= g_offsets[q] && slot < g_offsets[q] + g_counts[q]) e = q;
        int n = (s * 389 + 5) % DD;
        for (int k = lane; k < FF; k += 32) {
            float a = __bfloat162float(g_hid_hi[(size_t)slot * FF + k]) +
                      __bfloat162float(g_hid_lo[(size_t)slot * FF + k]);
            acc += a * We2[(size_t)e * FF * DD + (size_t)k * DD + n];
        }
        for (int o = 16; o > 0; o >>= 1) acc += __shfl_down_sync(0xffffffffu, acc, o);
        ref = g_wgt[slot] * (acc + be2[(size_t)e * DD + n]);
        got = g_partial[(size_t)slot * DD + n];
    } else if (stage == 2) {             // shared GEMM1: g_hs_hi/lo
        int m = (s * 137 + 3) % TT;
        int n = (s * 613 + 29) % FF;
        for (int k = lane; k < DD; k += 32)
            acc += h[(size_t)m * DD + k] * Ws1[(size_t)k * FF + n];
        for (int o = 16; o > 0; o >>= 1) acc += __shfl_down_sync(0xffffffffu, acc, o);
        ref = gelu_tanh(acc + bs1[n]);
        got = __bfloat162float(g_hs_hi[(size_t)m * FF + n]) +
              __bfloat162float(g_hs_lo[(size_t)m * FF + n]);
    } else {                             // shared GEMM2 + combine: out
        int m = (s * 541 + 11) % TT;
        int n = (s * 257 + 19) % DD;
        for (int k = lane; k < FF; k += 32) {
            float a = __bfloat162float(g_hs_hi[(size_t)m * FF + k]) +
                      __bfloat162float(g_hs_lo[(size_t)m * FF + k]);
            acc += a * Ws2[(size_t)k * DD + n];
        }
        for (int o = 16; o > 0; o >>= 1) acc += __shfl_down_sync(0xffffffffu, acc, o);
        if (lane == 0) {
            int p0 = g_posmap[2 * m], p1 = g_posmap[2 * m + 1];
            ref = acc + bs2[n] + g_partial[(size_t)p0 * DD + n] + g_partial[(size_t)p1 * DD + n];
            got = out[(size_t)m * DD + n];
        }
    }
    if (lane == 0) {
        float d = fabsf(ref - got);
        if (!(d <= 1e-2f * fmaxf(1.f, fabsf(ref)))) g_fail = 1;   // NaN-safe: NaN fails
    }
}

// ======================= FFMA fallback GEMM (R1, proven) =======================
template <int MODE>
__global__ void __launch_bounds__(256, 2)
gemm_tile(const float* __restrict__ Aext, const float* __restrict__ W,
          const float* __restrict__ bias, float* __restrict__ dout) {
    if (g_fail == 0) return;    // HMMA verified good -> skip
    const int Kd = (MODE == 0 || MODE == 2) ? DD : FF;
    const int Nd = (MODE == 0 || MODE == 2) ? FF : DD;
    const int e  = blockIdx.z;
    const int n0 = blockIdx.x * 128;
    const int m0 = blockIdx.y * 128;

    int cnt = 0, base = 0;
    if (MODE <= 1) {
        cnt = g_counts[e];
        base = g_offsets[e];
        if (m0 >= cnt) return;
    }

    const float* Bmat;
    const float* bvec;
    if (MODE == 0)      { Bmat = W + (size_t)e * DD * FF; bvec = bias + (size_t)e * FF; }
    else if (MODE == 1) { Bmat = W + (size_t)e * FF * DD; bvec = bias + (size_t)e * DD; }
    else                { Bmat = W; bvec = bias; }

    __shared__ float As[8][128];
    __shared__ float Bs[8][128];
    __shared__ const float* Ap[128];

    const int tid = threadIdx.x;
    for (int r = tid; r < 128; r += 256) {
        int mr = m0 + r;
        const float* p;
        if (MODE == 0) {
            int mm = (mr < cnt) ? mr : (cnt - 1);
            p = Aext + (size_t)g_perm[base + mm] * DD;
        } else if (MODE == 1) {
            int mm = (mr < cnt) ? mr : (cnt - 1);
            p = g_hid + (size_t)(base + mm) * FF;
        } else if (MODE == 2) {
            p = Aext + (size_t)mr * DD;
        } else {
            p = g_hid_s + (size_t)mr * FF;
        }
        Ap[r] = p;
    }
    __syncthreads();

    const int tx = tid & 15, ty = tid >> 4;
    const int aRow = tid >> 1, aCol = (tid & 1) * 4;
    const int bRow = tid >> 5, bCol = (tid & 31) * 4;

    float c[8][8];
#pragma unroll
    for (int i = 0; i < 8; i++)
#pragma unroll
        for (int j = 0; j < 8; j++) c[i][j] = 0.f;

    for (int kt = 0; kt < Kd; kt += 8) {
        float4 av = *(const float4*)(Ap[aRow] + kt + aCol);
        As[aCol + 0][aRow] = av.x;
        As[aCol + 1][aRow] = av.y;
        As[aCol + 2][aRow] = av.z;
        As[aCol + 3][aRow] = av.w;
        float4 bv = *(const float4*)(Bmat + (size_t)(kt + bRow) * Nd + n0 + bCol);
        *(float4*)&Bs[bRow][bCol] = bv;
        __syncthreads();
#pragma unroll
        for (int k = 0; k < 8; k++) {
            float4 a0 = *(float4*)&As[k][ty * 8];
            float4 a1 = *(float4*)&As[k][ty * 8 + 4];
            float4 b0 = *(float4*)&Bs[k][tx * 8];
            float4 b1 = *(float4*)&Bs[k][tx * 8 + 4];
            float ra[8] = {a0.x, a0.y, a0.z, a0.w, a1.x, a1.y, a1.z, a1.w};
            float rb[8] = {b0.x, b0.y, b0.z, b0.w, b1.x, b1.y, b1.z, b1.w};
#pragma unroll
            for (int i = 0; i < 8; i++)
#pragma unroll
                for (int j = 0; j < 8; j++) c[i][j] = fmaf(ra[i], rb[j], c[i][j]);
        }
        __syncthreads();
    }

#pragma unroll
    for (int i = 0; i < 8; i++) {
        int mr = m0 + ty * 8 + i;
        if (MODE <= 1 && mr >= cnt) continue;
        if (MODE == 0) {
            float* crow = g_hid + (size_t)(base + mr) * FF;
#pragma unroll
            for (int j = 0; j < 8; j++) {
                int n = n0 + tx * 8 + j;
                crow[n] = gelu_tanh(c[i][j] + bvec[n]);
            }
        } else if (MODE == 1) {
            float w = g_wgt[base + mr];
            float* crow = g_partial + (size_t)(base + mr) * DD;
#pragma unroll
            for (int j = 0; j < 8; j++) {
                int n = n0 + tx * 8 + j;
                crow[n] = w * (c[i][j] + bvec[n]);
            }
        } else if (MODE == 2) {
            float* crow = g_hid_s + (size_t)mr * FF;
#pragma unroll
            for (int j = 0; j < 8; j++) {
                int n = n0 + tx * 8 + j;
                crow[n] = gelu_tanh(c[i][j] + bvec[n]);
            }
        } else {
            int p0 = g_posmap[2 * mr], p1 = g_posmap[2 * mr + 1];
            const float* r0 = g_partial + (size_t)p0 * DD;
            const float* r1 = g_partial + (size_t)p1 * DD;
            float* crow = dout + (size_t)mr * DD;
#pragma unroll
            for (int j = 0; j < 8; j++) {
                int n = n0 + tx * 8 + j;
                crow[n] = c[i][j] + bvec[n] + r0[n] + r1[n];
            }
        }
    }
}

// ======================= launch =======================
extern "C" void kernel_launch(void* const* d_in, const int* in_sizes, int n_in,
                              void* d_out, int out_size) {
    const float* h   = (const float*)d_in[0];
    const float* Wr  = (const float*)d_in[1];
    const float* br  = (const float*)d_in[2];
    const float* We1 = (const float*)d_in[3];
    const float* be1 = (const float*)d_in[4];
    const float* We2 = (const float*)d_in[5];
    const float* be2 = (const float*)d_in[6];
    const float* Ws1 = (const float*)d_in[7];
    const float* bs1 = (const float*)d_in[8];
    const float* Ws2 = (const float*)d_in[9];
    const float* bs2 = (const float*)d_in[10];
    float* out = (float*)d_out;

    init_kernel<<<1, 32>>>(out, out_size);
    router_kernel<<<TT / 8, 256>>>(h, Wr, br);
    scan_kernel<<<1, 32>>>();
    scatter_kernel<<<TT / 256, 256>>>();

    // ---- HMMA attempt (only exotic op: mma.sync) ----
    conv_h_kernel<<<(TT * DD / 4 + 255) / 256, 256>>>(h);
    transpose_split<<<dim3(DD / 32, FF / 32, EE), dim3(32, 8)>>>(We1, g_We1t_hi, g_We1t_lo, DD, FF);
    transpose_split<<<dim3(FF / 32, DD / 32, EE), dim3(32, 8)>>>(We2, g_We2t_hi, g_We2t_lo, FF, DD);
    transpose_split<<<dim3(DD / 32, FF / 32, 1), dim3(32, 8)>>>(Ws1, g_Ws1t_hi, g_Ws1t_lo, DD, FF);
    transpose_split<<<dim3(FF / 32, DD / 32, 1), dim3(32, 8)>>>(Ws2, g_Ws2t_hi, g_Ws2t_lo, FF, DD);
    gemm_mm<0><<<dim3(FF / 128, TT / 128, EE), 256>>>(be1, nullptr);
    gemm_mm<1><<<dim3(DD / 128, TT / 128, EE), 256>>>(be2, nullptr);
    gemm_mm<2><<<dim3(FF / 128, TT / 128, 1), 256>>>(bs1, nullptr);
    gemm_mm<3><<<dim3(DD / 128, TT / 128, 1), 256>>>(bs2, out);

    // ---- verify HMMA result on 512 samples ----
    check_kernel<<<64, 256>>>(h, We1, be1, We2, be2, Ws1, bs1, Ws2, bs2, out);

    // ---- FFMA fallback (early-exits when HMMA verified) ----
    gemm_tile<0><<<dim3(FF / 128, TT / 128, EE), 256>>>(h, We1, be1, nullptr);
    gemm_tile<1><<<dim3(DD / 128, TT / 128, EE), 256>>>(nullptr, We2, be2, nullptr);
    gemm_tile<2><<<dim3(FF / 128, TT / 128, 1), 256>>>(h, Ws1, bs1, nullptr);
    gemm_tile<3><<<dim3(DD / 128, TT / 128, 1), 256>>>(nullptr, Ws2, bs2, out);
}

// round 15
// speedup vs baseline: 3.5551x; 3.5551x over previous
#include <cuda_runtime.h>
#include <cuda_bf16.h>
#include <math.h>
#include <stdint.h>

#define TT 4096   // tokens
#define DD 1024   // d_model
#define FF 4096   // d_ff
#define EE 8      // experts
#define SLOTS (TT*2)

// ======================= helpers =======================
__device__ __forceinline__ void mma_bf16(float* c, const uint32_t* a, uint32_t b0, uint32_t b1) {
    asm volatile("mma.sync.aligned.m16n8k16.row.col.f32.bf16.bf16.f32 "
        "{%0,%1,%2,%3}, {%4,%5,%6,%7}, {%8,%9}, {%0,%1,%2,%3};"
        : "+f"(c[0]), "+f"(c[1]), "+f"(c[2]), "+f"(c[3])
        : "r"(a[0]), "r"(a[1]), "r"(a[2]), "r"(a[3]), "r"(b0), "r"(b1));
}

// ======================= scratch =======================
// fp32 fallback buffers
__device__ float g_hid[(size_t)SLOTS * FF];
__device__ float g_hid_s[(size_t)TT * FF];
// bf16 split buffers (HMMA path)
__device__ __align__(256) __nv_bfloat16 g_h_hi[(size_t)TT * DD];
__device__ __align__(256) __nv_bfloat16 g_h_lo[(size_t)TT * DD];
__device__ __align__(256) __nv_bfloat16 g_We1t_hi[(size_t)EE * FF * DD];
__device__ __align__(256) __nv_bfloat16 g_We1t_lo[(size_t)EE * FF * DD];
__device__ __align__(256) __nv_bfloat16 g_We2t_hi[(size_t)EE * DD * FF];
__device__ __align__(256) __nv_bfloat16 g_We2t_lo[(size_t)EE * DD * FF];
__device__ __align__(256) __nv_bfloat16 g_Ws1t_hi[(size_t)FF * DD];
__device__ __align__(256) __nv_bfloat16 g_Ws1t_lo[(size_t)FF * DD];
__device__ __align__(256) __nv_bfloat16 g_Ws2t_hi[(size_t)DD * FF];
__device__ __align__(256) __nv_bfloat16 g_Ws2t_lo[(size_t)DD * FF];
__device__ __align__(256) __nv_bfloat16 g_hid_hi[(size_t)SLOTS * FF];
__device__ __align__(256) __nv_bfloat16 g_hid_lo[(size_t)SLOTS * FF];
__device__ __align__(256) __nv_bfloat16 g_hs_hi[(size_t)TT * FF];
__device__ __align__(256) __nv_bfloat16 g_hs_lo[(size_t)TT * FF];
__device__ __align__(256) float g_partial[(size_t)SLOTS * DD];   // shared by both paths (stream-ordered)
// routing
__device__ int   g_perm[SLOTS];
__device__ float g_wgt[SLOTS];
__device__ int   g_posmap[SLOTS];
__device__ int   g_tok_e[SLOTS];
__device__ float g_tok_w[SLOTS];
__device__ int   g_counts[EE];
__device__ int   g_offsets[EE];
__device__ int   g_cursor[EE];
__device__ int   g_fail;

__device__ __forceinline__ float gelu_tanh(float x) {
    float x3 = x * x * x;
    float t = tanhf(0.7978845608028654f * (x + 0.044715f * x3));
    return 0.5f * x * (1.0f + t);
}
__device__ __forceinline__ void split_bf16(float v, __nv_bfloat16& hi, __nv_bfloat16& lo) {
    hi = __float2bfloat16(v);
    lo = __float2bfloat16(v - __bfloat162float(hi));
}

// ======================= small kernels =======================
__global__ void init_kernel(float* out, int out_size) {
    if (threadIdx.x < EE) g_counts[threadIdx.x] = 0;
    if (threadIdx.x == 0) {
        g_fail = 0;
        if (out_size > TT * DD) out[TT * DD] = 0.125f;   // mean softmax = 1/E exactly
    }
}

__global__ void router_kernel(const float* __restrict__ h,
                              const float* __restrict__ Wr,
                              const float* __restrict__ br) {
    int warp = (blockIdx.x * blockDim.x + threadIdx.x) >> 5;
    int lane = threadIdx.x & 31;
    if (warp >= TT) return;
    const float* hrow = h + (size_t)warp * DD;
    float s[EE];
#pragma unroll
    for (int e = 0; e < EE; e++) s[e] = 0.f;
    for (int d = lane; d < DD; d += 32) {
        float hv = hrow[d];
        const float4* w4 = (const float4*)(Wr + (size_t)d * EE);
        float4 a = w4[0], b = w4[1];
        s[0] += hv * a.x; s[1] += hv * a.y; s[2] += hv * a.z; s[3] += hv * a.w;
        s[4] += hv * b.x; s[5] += hv * b.y; s[6] += hv * b.z; s[7] += hv * b.w;
    }
#pragma unroll
    for (int e = 0; e < EE; e++)
#pragma unroll
        for (int o = 16; o > 0; o >>= 1) s[e] += __shfl_down_sync(0xffffffffu, s[e], o);
    if (lane == 0) {
        float l[EE];
#pragma unroll
        for (int e = 0; e < EE; e++) l[e] = s[e] + br[e];
        float m = l[0];
#pragma unroll
        for (int e = 1; e < EE; e++) m = fmaxf(m, l[e]);
        float p[EE], sum = 0.f;
#pragma unroll
        for (int e = 0; e < EE; e++) { p[e] = expf(l[e] - m); sum += p[e]; }
        int i0 = 0;
#pragma unroll
        for (int e = 1; e < EE; e++) if (l[e] > l[i0]) i0 = e;
        int i1 = -1;
#pragma unroll
        for (int e = 0; e < EE; e++) {
            if (e == i0) continue;
            if (i1 < 0 || l[e] > l[i1]) i1 = e;
        }
        float inv = 1.f / sum;
        g_tok_e[warp * 2 + 0] = i0; g_tok_w[warp * 2 + 0] = p[i0] * inv;
        g_tok_e[warp * 2 + 1] = i1; g_tok_w[warp * 2 + 1] = p[i1] * inv;
        atomicAdd(&g_counts[i0], 1);
        atomicAdd(&g_counts[i1], 1);
    }
}

__global__ void scan_kernel() {
    if (threadIdx.x == 0) {
        int acc = 0;
        for (int e = 0; e < EE; e++) { g_offsets[e] = acc; g_cursor[e] = acc; acc += g_counts[e]; }
    }
}

__global__ void scatter_kernel() {
    int t = blockIdx.x * blockDim.x + threadIdx.x;
    if (t >= TT) return;
#pragma unroll
    for (int k = 0; k < 2; k++) {
        int e = g_tok_e[t * 2 + k];
        int pos = atomicAdd(&g_cursor[e], 1);
        g_perm[pos] = t;
        g_wgt[pos] = g_tok_w[t * 2 + k];
        g_posmap[t * 2 + k] = pos;
    }
}

__global__ void conv_h_kernel(const float* __restrict__ h) {
    int i4 = blockIdx.x * blockDim.x + threadIdx.x;
    if (i4 >= TT * DD / 4) return;
    float4 v = ((const float4*)h)[i4];
    __nv_bfloat16 hh[4], ll[4];
    split_bf16(v.x, hh[0], ll[0]); split_bf16(v.y, hh[1], ll[1]);
    split_bf16(v.z, hh[2], ll[2]); split_bf16(v.w, hh[3], ll[3]);
    ((uint2*)g_h_hi)[i4] = *(uint2*)hh;
    ((uint2*)g_h_lo)[i4] = *(uint2*)ll;
}

// W[e][K][N] fp32 -> Wt_hi/lo[e][N][K] bf16.
// SEL picks destination globals IN DEVICE CODE — device symbols must never be
// passed as kernel arguments from host (host shadow address + ATS = silent
// writes to host memory; root cause of the R7-R14 zero outputs).
template <int SEL>
__global__ void transpose_split(const float* __restrict__ W) {
    constexpr int K = (SEL == 0 || SEL == 2) ? DD : FF;
    constexpr int N = (SEL == 0 || SEL == 2) ? FF : DD;
    __nv_bfloat16 *Oh, *Ol;
    if (SEL == 0)      { Oh = g_We1t_hi; Ol = g_We1t_lo; }
    else if (SEL == 1) { Oh = g_We2t_hi; Ol = g_We2t_lo; }
    else if (SEL == 2) { Oh = g_Ws1t_hi; Ol = g_Ws1t_lo; }
    else               { Oh = g_Ws2t_hi; Ol = g_Ws2t_lo; }

    __shared__ float s[32][33];
    int e = blockIdx.z;
    W  += (size_t)e * K * N;
    Oh += (size_t)e * N * K;
    Ol += (size_t)e * N * K;
    int k0 = blockIdx.x * 32, n0 = blockIdx.y * 32;
    int tx = threadIdx.x, ty = threadIdx.y;  // 32 x 8
#pragma unroll
    for (int i = 0; i < 4; i++)
        s[ty + i * 8][tx] = W[(size_t)(k0 + ty + i * 8) * N + n0 + tx];
    __syncthreads();
#pragma unroll
    for (int i = 0; i < 4; i++) {
        int n = n0 + ty + i * 8, k = k0 + tx;
        float v = s[tx][ty + i * 8];
        __nv_bfloat16 hi, lo;
        split_bf16(v, hi, lo);
        Oh[(size_t)n * K + k] = hi;
        Ol[(size_t)n * K + k] = lo;
    }
}

// ======================= HMMA GEMM: plain LDG/STS + mma.sync =======================
#define KC 16
#define TILE_B 4096
#define STAGE_B (4 * TILE_B)
#define SWZ(row, kb) ((row) * 32 + (((((kb) >> 4) ^ (((row) >> 2) & 1))) << 4) + ((kb) & 15))

template <int MODE>
__global__ void __launch_bounds__(256)
gemm_mm(const float* __restrict__ bias, float* __restrict__ dout) {
    const int Ktot = (MODE == 0 || MODE == 2) ? DD : FF;
    const int CH = Ktot / KC;
    const int e = blockIdx.z;
    const int n0 = blockIdx.x * 128;
    const int m0 = blockIdx.y * 128;

    int cnt = 0, base = 0;
    if (MODE <= 1) {
        cnt = g_counts[e];
        base = g_offsets[e];
        if (m0 >= cnt) return;
    }

    __shared__ __align__(16) char sm[STAGE_B];           // 16 KB
    __shared__ const __nv_bfloat16* ApH[128];
    __shared__ const __nv_bfloat16* ApL[128];

    const int tid = threadIdx.x, wid = tid >> 5, lane = tid & 31;

    const __nv_bfloat16 *Bhi, *Blo;
    const float* bvec;
    if (MODE == 0)      { Bhi = g_We1t_hi + (size_t)e * FF * DD; Blo = g_We1t_lo + (size_t)e * FF * DD; bvec = bias + (size_t)e * FF; }
    else if (MODE == 1) { Bhi = g_We2t_hi + (size_t)e * DD * FF; Blo = g_We2t_lo + (size_t)e * DD * FF; bvec = bias + (size_t)e * DD; }
    else if (MODE == 2) { Bhi = g_Ws1t_hi; Blo = g_Ws1t_lo; bvec = bias; }
    else                { Bhi = g_Ws2t_hi; Blo = g_Ws2t_lo; bvec = bias; }

    for (int r = tid; r < 128; r += 256) {
        int mr = m0 + r;
        const __nv_bfloat16 *ph, *pl;
        if (MODE == 0) {
            int mm = (mr < cnt) ? mr : (cnt - 1);
            int t = g_perm[base + mm];
            ph = g_h_hi + (size_t)t * DD; pl = g_h_lo + (size_t)t * DD;
        } else if (MODE == 1) {
            int mm = (mr < cnt) ? mr : (cnt - 1);
            ph = g_hid_hi + (size_t)(base + mm) * FF; pl = g_hid_lo + (size_t)(base + mm) * FF;
        } else if (MODE == 2) {
            ph = g_h_hi + (size_t)mr * DD; pl = g_h_lo + (size_t)mr * DD;
        } else {
            ph = g_hs_hi + (size_t)mr * FF; pl = g_hs_lo + (size_t)mr * FF;
        }
        ApH[r] = ph; ApL[r] = pl;
    }
    __syncthreads();

    int ti[4], rr[4], cc[4];
#pragma unroll
    for (int i = 0; i < 4; i++) {
        int u = tid + i * 256;
        ti[i] = u >> 8;
        int w = u & 255;
        rr[i] = w >> 1; cc[i] = w & 1;
    }

    auto fetch = [&](int c, uint4* v) {
        const int k0 = c * KC;
#pragma unroll
        for (int i = 0; i < 4; i++) {
            const __nv_bfloat16* src;
            if (ti[i] == 0)      src = ApH[rr[i]] + k0 + cc[i] * 8;
            else if (ti[i] == 1) src = ApL[rr[i]] + k0 + cc[i] * 8;
            else if (ti[i] == 2) src = Bhi + (size_t)(n0 + rr[i]) * Ktot + k0 + cc[i] * 8;
            else                 src = Blo + (size_t)(n0 + rr[i]) * Ktot + k0 + cc[i] * 8;
            v[i] = *(const uint4*)src;
        }
    };
    auto store_sm = [&](const uint4* v) {
#pragma unroll
        for (int i = 0; i < 4; i++)
            *(uint4*)(sm + ti[i] * TILE_B + rr[i] * 32 + ((cc[i] ^ ((rr[i] >> 2) & 1)) << 4)) = v[i];
    };

    const int wm = wid & 1, wn = wid >> 1;
    const int gid = lane >> 2, t2 = lane & 3;

    float acc[4][4][4];
#pragma unroll
    for (int i = 0; i < 4; i++)
#pragma unroll
        for (int j = 0; j < 4; j++)
#pragma unroll
            for (int q = 0; q < 4; q++) acc[i][j][q] = 0.f;

    uint4 cur[4], nxt[4];
    fetch(0, cur);

    for (int c = 0; c < CH; c++) {
        store_sm(cur);
        __syncthreads();
        if (c + 1 < CH) fetch(c + 1, nxt);

        const char* tAH = sm;
        const char* tAL = sm + TILE_B;
        const char* tBH = sm + 2 * TILE_B;
        const char* tBL = sm + 3 * TILE_B;
        const int kb0 = t2 * 4, kb1 = t2 * 4 + 16;

        uint32_t ahi[4][4], alo[4][4], bh0[4], bh1[4], bl0[4], bl1[4];
#pragma unroll
        for (int im = 0; im < 4; im++) {
            const int r0 = wm * 64 + im * 16 + gid;
            const int r1 = r0 + 8;
            ahi[im][0] = *(const uint32_t*)(tAH + SWZ(r0, kb0));
            ahi[im][1] = *(const uint32_t*)(tAH + SWZ(r1, kb0));
            ahi[im][2] = *(const uint32_t*)(tAH + SWZ(r0, kb1));
            ahi[im][3] = *(const uint32_t*)(tAH + SWZ(r1, kb1));
            alo[im][0] = *(const uint32_t*)(tAL + SWZ(r0, kb0));
            alo[im][1] = *(const uint32_t*)(tAL + SWZ(r1, kb0));
            alo[im][2] = *(const uint32_t*)(tAL + SWZ(r0, kb1));
            alo[im][3] = *(const uint32_t*)(tAL + SWZ(r1, kb1));
        }
#pragma unroll
        for (int nb = 0; nb < 4; nb++) {
            const int n = wn * 32 + nb * 8 + gid;
            bh0[nb] = *(const uint32_t*)(tBH + SWZ(n, kb0));
            bh1[nb] = *(const uint32_t*)(tBH + SWZ(n, kb1));
            bl0[nb] = *(const uint32_t*)(tBL + SWZ(n, kb0));
            bl1[nb] = *(const uint32_t*)(tBL + SWZ(n, kb1));
        }
#pragma unroll
        for (int im = 0; im < 4; im++)
#pragma unroll
            for (int nb = 0; nb < 4; nb++) {
                mma_bf16(acc[im][nb], ahi[im], bh0[nb], bh1[nb]);
                mma_bf16(acc[im][nb], ahi[im], bl0[nb], bl1[nb]);
                mma_bf16(acc[im][nb], alo[im], bh0[nb], bh1[nb]);
            }
        __syncthreads();
#pragma unroll
        for (int i = 0; i < 4; i++) cur[i] = nxt[i];
    }

    // ---------------- epilogue ----------------
#pragma unroll
    for (int im = 0; im < 4; im++) {
        const int tr = wm * 64 + im * 16 + gid;
#pragma unroll
        for (int half = 0; half < 2; half++) {
            const int row = tr + half * 8;
            const int mr = m0 + row;
            if (MODE <= 1 && mr >= cnt) continue;
#pragma unroll
            for (int nb = 0; nb < 4; nb++) {
                const int col = n0 + wn * 32 + nb * 8 + t2 * 2;
                float v0 = acc[im][nb][half * 2 + 0] + bvec[col];
                float v1 = acc[im][nb][half * 2 + 1] + bvec[col + 1];
                if (MODE == 0 || MODE == 2) {
                    v0 = gelu_tanh(v0); v1 = gelu_tanh(v1);
                    __nv_bfloat16 h0, l0, h1, l1;
                    split_bf16(v0, h0, l0); split_bf16(v1, h1, l1);
                    uint32_t ph = (uint32_t)__bfloat16_as_ushort(h0) | ((uint32_t)__bfloat16_as_ushort(h1) << 16);
                    uint32_t pl = (uint32_t)__bfloat16_as_ushort(l0) | ((uint32_t)__bfloat16_as_ushort(l1) << 16);
                    size_t rowoff = (MODE == 0) ? (size_t)(base + mr) * FF : (size_t)mr * FF;
                    __nv_bfloat16* dh = (MODE == 0 ? g_hid_hi : g_hs_hi) + rowoff + col;
                    __nv_bfloat16* dl = (MODE == 0 ? g_hid_lo : g_hs_lo) + rowoff + col;
                    *(uint32_t*)dh = ph;
                    *(uint32_t*)dl = pl;
                } else if (MODE == 1) {
                    float w = g_wgt[base + mr];
                    float2* dst = (float2*)(g_partial + (size_t)(base + mr) * DD + col);
                    *dst = make_float2(w * v0, w * v1);
                } else {
                    int p0 = g_posmap[2 * mr], p1 = g_posmap[2 * mr + 1];
                    const float2 r0 = *(const float2*)(g_partial + (size_t)p0 * DD + col);
                    const float2 r1 = *(const float2*)(g_partial + (size_t)p1 * DD + col);
                    float2* dst = (float2*)(dout + (size_t)mr * DD + col);
                    *dst = make_float2(v0 + r0.x + r1.x, v1 + r0.y + r1.y);
                }
            }
        }
    }
}

// ======================= checker: sample-verify all 4 HMMA stages =======================
__global__ void check_kernel(const float* __restrict__ h,
                             const float* __restrict__ We1, const float* __restrict__ be1,
                             const float* __restrict__ We2, const float* __restrict__ be2,
                             const float* __restrict__ Ws1, const float* __restrict__ bs1,
                             const float* __restrict__ Ws2, const float* __restrict__ bs2,
                             const float* __restrict__ out) {
    int gwarp = (blockIdx.x * blockDim.x + threadIdx.x) >> 5;   // 0..511
    int lane = threadIdx.x & 31;
    int stage = gwarp & 3, s = gwarp >> 2;                      // 128 samples/stage

    float ref = 0.f, got = 0.f, acc = 0.f;
    if (stage == 0) {
        int slot = (s * 977 + 13) % SLOTS;
        int e = 0;
        for (int q = 0; q < EE; q++)
            if (slot >= g_offsets[q] && slot < g_offsets[q] + g_counts[q]) e = q;
        int tok = g_perm[slot];
        int n = (s * 613 + 17) % FF;
        for (int k = lane; k < DD; k += 32)
            acc += h[(size_t)tok * DD + k] * We1[(size_t)e * DD * FF + (size_t)k * FF + n];
        for (int o = 16; o > 0; o >>= 1) acc += __shfl_down_sync(0xffffffffu, acc, o);
        ref = gelu_tanh(acc + be1[(size_t)e * FF + n]);
        got = __bfloat162float(g_hid_hi[(size_t)slot * FF + n]) +
              __bfloat162float(g_hid_lo[(size_t)slot * FF + n]);
    } else if (stage == 1) {
        int slot = (s * 769 + 7) % SLOTS;
        int e = 0;
        for (int q = 0; q < EE; q++)
            if (slot >= g_offsets[q] && slot < g_offsets[q] + g_counts[q]) e = q;
        int n = (s * 389 + 5) % DD;
        for (int k = lane; k < FF; k += 32) {
            float a = __bfloat162float(g_hid_hi[(size_t)slot * FF + k]) +
                      __bfloat162float(g_hid_lo[(size_t)slot * FF + k]);
            acc += a * We2[(size_t)e * FF * DD + (size_t)k * DD + n];
        }
        for (int o = 16; o > 0; o >>= 1) acc += __shfl_down_sync(0xffffffffu, acc, o);
        ref = g_wgt[slot] * (acc + be2[(size_t)e * DD + n]);
        got = g_partial[(size_t)slot * DD + n];
    } else if (stage == 2) {
        int m = (s * 137 + 3) % TT;
        int n = (s * 613 + 29) % FF;
        for (int k = lane; k < DD; k += 32)
            acc += h[(size_t)m * DD + k] * Ws1[(size_t)k * FF + n];
        for (int o = 16; o > 0; o >>= 1) acc += __shfl_down_sync(0xffffffffu, acc, o);
        ref = gelu_tanh(acc + bs1[n]);
        got = __bfloat162float(g_hs_hi[(size_t)m * FF + n]) +
              __bfloat162float(g_hs_lo[(size_t)m * FF + n]);
    } else {
        int m = (s * 541 + 11) % TT;
        int n = (s * 257 + 19) % DD;
        for (int k = lane; k < FF; k += 32) {
            float a = __bfloat162float(g_hs_hi[(size_t)m * FF + k]) +
                      __bfloat162float(g_hs_lo[(size_t)m * FF + k]);
            acc += a * Ws2[(size_t)k * DD + n];
        }
        for (int o = 16; o > 0; o >>= 1) acc += __shfl_down_sync(0xffffffffu, acc, o);
        if (lane == 0) {
            int p0 = g_posmap[2 * m], p1 = g_posmap[2 * m + 1];
            ref = acc + bs2[n] + g_partial[(size_t)p0 * DD + n] + g_partial[(size_t)p1 * DD + n];
            got = out[(size_t)m * DD + n];
        }
    }
    if (lane == 0) {
        float d = fabsf(ref - got);
        if (!(d <= 1e-2f * fmaxf(1.f, fabsf(ref)))) g_fail = 1;   // NaN-safe: NaN fails
    }
}

// ======================= FFMA fallback GEMM (R1, proven) =======================
template <int MODE>
__global__ void __launch_bounds__(256, 2)
gemm_tile(const float* __restrict__ Aext, const float* __restrict__ W,
          const float* __restrict__ bias, float* __restrict__ dout) {
    if (g_fail == 0) return;    // HMMA verified good -> skip
    const int Kd = (MODE == 0 || MODE == 2) ? DD : FF;
    const int Nd = (MODE == 0 || MODE == 2) ? FF : DD;
    const int e  = blockIdx.z;
    const int n0 = blockIdx.x * 128;
    const int m0 = blockIdx.y * 128;

    int cnt = 0, base = 0;
    if (MODE <= 1) {
        cnt = g_counts[e];
        base = g_offsets[e];
        if (m0 >= cnt) return;
    }

    const float* Bmat;
    const float* bvec;
    if (MODE == 0)      { Bmat = W + (size_t)e * DD * FF; bvec = bias + (size_t)e * FF; }
    else if (MODE == 1) { Bmat = W + (size_t)e * FF * DD; bvec = bias + (size_t)e * DD; }
    else                { Bmat = W; bvec = bias; }

    __shared__ float As[8][128];
    __shared__ float Bs[8][128];
    __shared__ const float* Ap[128];

    const int tid = threadIdx.x;
    for (int r = tid; r < 128; r += 256) {
        int mr = m0 + r;
        const float* p;
        if (MODE == 0) {
            int mm = (mr < cnt) ? mr : (cnt - 1);
            p = Aext + (size_t)g_perm[base + mm] * DD;
        } else if (MODE == 1) {
            int mm = (mr < cnt) ? mr : (cnt - 1);
            p = g_hid + (size_t)(base + mm) * FF;
        } else if (MODE == 2) {
            p = Aext + (size_t)mr * DD;
        } else {
            p = g_hid_s + (size_t)mr * FF;
        }
        Ap[r] = p;
    }
    __syncthreads();

    const int tx = tid & 15, ty = tid >> 4;
    const int aRow = tid >> 1, aCol = (tid & 1) * 4;
    const int bRow = tid >> 5, bCol = (tid & 31) * 4;

    float c[8][8];
#pragma unroll
    for (int i = 0; i < 8; i++)
#pragma unroll
        for (int j = 0; j < 8; j++) c[i][j] = 0.f;

    for (int kt = 0; kt < Kd; kt += 8) {
        float4 av = *(const float4*)(Ap[aRow] + kt + aCol);
        As[aCol + 0][aRow] = av.x;
        As[aCol + 1][aRow] = av.y;
        As[aCol + 2][aRow] = av.z;
        As[aCol + 3][aRow] = av.w;
        float4 bv = *(const float4*)(Bmat + (size_t)(kt + bRow) * Nd + n0 + bCol);
        *(float4*)&Bs[bRow][bCol] = bv;
        __syncthreads();
#pragma unroll
        for (int k = 0; k < 8; k++) {
            float4 a0 = *(float4*)&As[k][ty * 8];
            float4 a1 = *(float4*)&As[k][ty * 8 + 4];
            float4 b0 = *(float4*)&Bs[k][tx * 8];
            float4 b1 = *(float4*)&Bs[k][tx * 8 + 4];
            float ra[8] = {a0.x, a0.y, a0.z, a0.w, a1.x, a1.y, a1.z, a1.w};
            float rb[8] = {b0.x, b0.y, b0.z, b0.w, b1.x, b1.y, b1.z, b1.w};
#pragma unroll
            for (int i = 0; i < 8; i++)
#pragma unroll
                for (int j = 0; j < 8; j++) c[i][j] = fmaf(ra[i], rb[j], c[i][j]);
        }
        __syncthreads();
    }

#pragma unroll
    for (int i = 0; i < 8; i++) {
        int mr = m0 + ty * 8 + i;
        if (MODE <= 1 && mr >= cnt) continue;
        if (MODE == 0) {
            float* crow = g_hid + (size_t)(base + mr) * FF;
#pragma unroll
            for (int j = 0; j < 8; j++) {
                int n = n0 + tx * 8 + j;
                crow[n] = gelu_tanh(c[i][j] + bvec[n]);
            }
        } else if (MODE == 1) {
            float w = g_wgt[base + mr];
            float* crow = g_partial + (size_t)(base + mr) * DD;
#pragma unroll
            for (int j = 0; j < 8; j++) {
                int n = n0 + tx * 8 + j;
                crow[n] = w * (c[i][j] + bvec[n]);
            }
        } else if (MODE == 2) {
            float* crow = g_hid_s + (size_t)mr * FF;
#pragma unroll
            for (int j = 0; j < 8; j++) {
                int n = n0 + tx * 8 + j;
                crow[n] = gelu_tanh(c[i][j] + bvec[n]);
            }
        } else {
            int p0 = g_posmap[2 * mr], p1 = g_posmap[2 * mr + 1];
            const float* r0 = g_partial + (size_t)p0 * DD;
            const float* r1 = g_partial + (size_t)p1 * DD;
            float* crow = dout + (size_t)mr * DD;
#pragma unroll
            for (int j = 0; j < 8; j++) {
                int n = n0 + tx * 8 + j;
                crow[n] = c[i][j] + bvec[n] + r0[n] + r1[n];
            }
        }
    }
}

// ======================= launch =======================
extern "C" void kernel_launch(void* const* d_in, const int* in_sizes, int n_in,
                              void* d_out, int out_size) {
    const float* h   = (const float*)d_in[0];
    const float* Wr  = (const float*)d_in[1];
    const float* br  = (const float*)d_in[2];
    const float* We1 = (const float*)d_in[3];
    const float* be1 = (const float*)d_in[4];
    const float* We2 = (const float*)d_in[5];
    const float* be2 = (const float*)d_in[6];
    const float* Ws1 = (const float*)d_in[7];
    const float* bs1 = (const float*)d_in[8];
    const float* Ws2 = (const float*)d_in[9];
    const float* bs2 = (const float*)d_in[10];
    float* out = (float*)d_out;

    init_kernel<<<1, 32>>>(out, out_size);
    router_kernel<<<TT / 8, 256>>>(h, Wr, br);
    scan_kernel<<<1, 32>>>();
    scatter_kernel<<<TT / 256, 256>>>();

    // ---- HMMA path: only harness pointers cross the launch boundary ----
    conv_h_kernel<<<(TT * DD / 4 + 255) / 256, 256>>>(h);
    transpose_split<0><<<dim3(DD / 32, FF / 32, EE), dim3(32, 8)>>>(We1);
    transpose_split<1><<<dim3(FF / 32, DD / 32, EE), dim3(32, 8)>>>(We2);
    transpose_split<2><<<dim3(DD / 32, FF / 32, 1), dim3(32, 8)>>>(Ws1);
    transpose_split<3><<<dim3(FF / 32, DD / 32, 1), dim3(32, 8)>>>(Ws2);
    gemm_mm<0><<<dim3(FF / 128, TT / 128, EE), 256>>>(be1, nullptr);
    gemm_mm<1><<<dim3(DD / 128, TT / 128, EE), 256>>>(be2, nullptr);
    gemm_mm<2><<<dim3(FF / 128, TT / 128, 1), 256>>>(bs1, nullptr);
    gemm_mm<3><<<dim3(DD / 128, TT / 128, 1), 256>>>(bs2, out);

    // ---- verify HMMA result on 512 samples ----
    check_kernel<<<64, 256>>>(h, We1, be1, We2, be2, Ws1, bs1, Ws2, bs2, out);

    // ---- FFMA fallback (early-exits when HMMA verified) ----
    gemm_tile<0><<<dim3(FF / 128, TT / 128, EE), 256>>>(h, We1, be1, nullptr);
    gemm_tile<1><<<dim3(DD / 128, TT / 128, EE), 256>>>(nullptr, We2, be2, nullptr);
    gemm_tile<2><<<dim3(FF / 128, TT / 128, 1), 256>>>(h, Ws1, bs1, nullptr);
    gemm_tile<3><<<dim3(DD / 128, TT / 128, 1), 256>>>(nullptr, Ws2, bs2, out);
}

// round 17
// speedup vs baseline: 4.6443x; 1.3064x over previous
#include <cuda_runtime.h>
#include <cuda_bf16.h>
#include <math.h>
#include <stdint.h>

#define TT 4096   // tokens
#define DD 1024   // d_model
#define FF 4096   // d_ff
#define EE 8      // experts
#define SLOTS (TT*2)

// ======================= helpers =======================
__device__ __forceinline__ uint32_t smem_to_u32(const void* p) {
    uint32_t a;
    asm("{ .reg .u64 t; cvta.to.shared.u64 t, %1; cvt.u32.u64 %0, t; }" : "=r"(a) : "l"(p));
    return a;
}
__device__ __forceinline__ void cp16(uint32_t dst, const void* src) {
    asm volatile("cp.async.cg.shared.global [%0], [%1], 16;" :: "r"(dst), "l"(src) : "memory");
}
#define CP_COMMIT() asm volatile("cp.async.commit_group;" ::: "memory")
#define CP_WAIT(n)  asm volatile("cp.async.wait_group %0;" :: "n"(n) : "memory")

__device__ __forceinline__ void ldm_x4(uint32_t addr, uint32_t* r) {
    asm volatile("ldmatrix.sync.aligned.m8n8.x4.shared.b16 {%0,%1,%2,%3}, [%4];"
        : "=r"(r[0]), "=r"(r[1]), "=r"(r[2]), "=r"(r[3]) : "r"(addr));
}
__device__ __forceinline__ void mma_bf16(float* c, const uint32_t* a, uint32_t b0, uint32_t b1) {
    asm volatile("mma.sync.aligned.m16n8k16.row.col.f32.bf16.bf16.f32 "
        "{%0,%1,%2,%3}, {%4,%5,%6,%7}, {%8,%9}, {%0,%1,%2,%3};"
        : "+f"(c[0]), "+f"(c[1]), "+f"(c[2]), "+f"(c[3])
        : "r"(a[0]), "r"(a[1]), "r"(a[2]), "r"(a[3]), "r"(b0), "r"(b1));
}

// ======================= scratch =======================
// fp32 fallback buffers
__device__ float g_hid[(size_t)SLOTS * FF];
__device__ float g_hid_s[(size_t)TT * FF];
// bf16 split buffers (HMMA path)
__device__ __align__(256) __nv_bfloat16 g_h_hi[(size_t)TT * DD];
__device__ __align__(256) __nv_bfloat16 g_h_lo[(size_t)TT * DD];
__device__ __align__(256) __nv_bfloat16 g_We1t_hi[(size_t)EE * FF * DD];
__device__ __align__(256) __nv_bfloat16 g_We1t_lo[(size_t)EE * FF * DD];
__device__ __align__(256) __nv_bfloat16 g_We2t_hi[(size_t)EE * DD * FF];
__device__ __align__(256) __nv_bfloat16 g_We2t_lo[(size_t)EE * DD * FF];
__device__ __align__(256) __nv_bfloat16 g_Ws1t_hi[(size_t)FF * DD];
__device__ __align__(256) __nv_bfloat16 g_Ws1t_lo[(size_t)FF * DD];
__device__ __align__(256) __nv_bfloat16 g_Ws2t_hi[(size_t)DD * FF];
__device__ __align__(256) __nv_bfloat16 g_Ws2t_lo[(size_t)DD * FF];
__device__ __align__(256) __nv_bfloat16 g_hid_hi[(size_t)SLOTS * FF];
__device__ __align__(256) __nv_bfloat16 g_hid_lo[(size_t)SLOTS * FF];
__device__ __align__(256) __nv_bfloat16 g_hs_hi[(size_t)TT * FF];
__device__ __align__(256) __nv_bfloat16 g_hs_lo[(size_t)TT * FF];
__device__ __align__(256) float g_partial[(size_t)SLOTS * DD];   // shared by both paths (stream-ordered)
// routing
__device__ int   g_perm[SLOTS];
__device__ float g_wgt[SLOTS];
__device__ int   g_posmap[SLOTS];
__device__ int   g_tok_e[SLOTS];
__device__ float g_tok_w[SLOTS];
__device__ int   g_counts[EE];
__device__ int   g_offsets[EE];
__device__ int   g_cursor[EE];
__device__ int   g_fail;

__device__ __forceinline__ float gelu_tanh(float x) {
    float x3 = x * x * x;
    float t = tanhf(0.7978845608028654f * (x + 0.044715f * x3));
    return 0.5f * x * (1.0f + t);
}
__device__ __forceinline__ void split_bf16(float v, __nv_bfloat16& hi, __nv_bfloat16& lo) {
    hi = __float2bfloat16(v);
    lo = __float2bfloat16(v - __bfloat162float(hi));
}

// ======================= small kernels =======================
__global__ void init_kernel(float* out, int out_size) {
    if (threadIdx.x < EE) g_counts[threadIdx.x] = 0;
    if (threadIdx.x == 0) {
        g_fail = 0;
        if (out_size > TT * DD) out[TT * DD] = 0.125f;   // mean softmax = 1/E exactly
    }
}

__global__ void router_kernel(const float* __restrict__ h,
                              const float* __restrict__ Wr,
                              const float* __restrict__ br) {
    int warp = (blockIdx.x * blockDim.x + threadIdx.x) >> 5;
    int lane = threadIdx.x & 31;
    if (warp >= TT) return;
    const float* hrow = h + (size_t)warp * DD;
    float s[EE];
#pragma unroll
    for (int e = 0; e < EE; e++) s[e] = 0.f;
    for (int d = lane; d < DD; d += 32) {
        float hv = hrow[d];
        const float4* w4 = (const float4*)(Wr + (size_t)d * EE);
        float4 a = w4[0], b = w4[1];
        s[0] += hv * a.x; s[1] += hv * a.y; s[2] += hv * a.z; s[3] += hv * a.w;
        s[4] += hv * b.x; s[5] += hv * b.y; s[6] += hv * b.z; s[7] += hv * b.w;
    }
#pragma unroll
    for (int e = 0; e < EE; e++)
#pragma unroll
        for (int o = 16; o > 0; o >>= 1) s[e] += __shfl_down_sync(0xffffffffu, s[e], o);
    if (lane == 0) {
        float l[EE];
#pragma unroll
        for (int e = 0; e < EE; e++) l[e] = s[e] + br[e];
        float m = l[0];
#pragma unroll
        for (int e = 1; e < EE; e++) m = fmaxf(m, l[e]);
        float p[EE], sum = 0.f;
#pragma unroll
        for (int e = 0; e < EE; e++) { p[e] = expf(l[e] - m); sum += p[e]; }
        int i0 = 0;
#pragma unroll
        for (int e = 1; e < EE; e++) if (l[e] > l[i0]) i0 = e;
        int i1 = -1;
#pragma unroll
        for (int e = 0; e < EE; e++) {
            if (e == i0) continue;
            if (i1 < 0 || l[e] > l[i1]) i1 = e;
        }
        float inv = 1.f / sum;
        g_tok_e[warp * 2 + 0] = i0; g_tok_w[warp * 2 + 0] = p[i0] * inv;
        g_tok_e[warp * 2 + 1] = i1; g_tok_w[warp * 2 + 1] = p[i1] * inv;
        atomicAdd(&g_counts[i0], 1);
        atomicAdd(&g_counts[i1], 1);
    }
}

__global__ void scan_kernel() {
    if (threadIdx.x == 0) {
        int acc = 0;
        for (int e = 0; e < EE; e++) { g_offsets[e] = acc; g_cursor[e] = acc; acc += g_counts[e]; }
    }
}

__global__ void scatter_kernel() {
    int t = blockIdx.x * blockDim.x + threadIdx.x;
    if (t >= TT) return;
#pragma unroll
    for (int k = 0; k < 2; k++) {
        int e = g_tok_e[t * 2 + k];
        int pos = atomicAdd(&g_cursor[e], 1);
        g_perm[pos] = t;
        g_wgt[pos] = g_tok_w[t * 2 + k];
        g_posmap[t * 2 + k] = pos;
    }
}

__global__ void conv_h_kernel(const float* __restrict__ h) {
    int i4 = blockIdx.x * blockDim.x + threadIdx.x;
    if (i4 >= TT * DD / 4) return;
    float4 v = ((const float4*)h)[i4];
    __nv_bfloat16 hh[4], ll[4];
    split_bf16(v.x, hh[0], ll[0]); split_bf16(v.y, hh[1], ll[1]);
    split_bf16(v.z, hh[2], ll[2]); split_bf16(v.w, hh[3], ll[3]);
    ((uint2*)g_h_hi)[i4] = *(uint2*)hh;
    ((uint2*)g_h_lo)[i4] = *(uint2*)ll;
}

// W[e][K][N] fp32 -> Wt_hi/lo[e][N][K] bf16.
// SEL picks destination globals IN DEVICE CODE — device symbols must never be
// passed as kernel args from host (host shadow + ATS = silent host writes).
template <int SEL>
__global__ void transpose_split(const float* __restrict__ W) {
    constexpr int K = (SEL == 0 || SEL == 2) ? DD : FF;
    constexpr int N = (SEL == 0 || SEL == 2) ? FF : DD;
    __nv_bfloat16 *Oh, *Ol;
    if (SEL == 0)      { Oh = g_We1t_hi; Ol = g_We1t_lo; }
    else if (SEL == 1) { Oh = g_We2t_hi; Ol = g_We2t_lo; }
    else if (SEL == 2) { Oh = g_Ws1t_hi; Ol = g_Ws1t_lo; }
    else               { Oh = g_Ws2t_hi; Ol = g_Ws2t_lo; }

    __shared__ float s[32][33];
    int e = blockIdx.z;
    W  += (size_t)e * K * N;
    Oh += (size_t)e * N * K;
    Ol += (size_t)e * N * K;
    int k0 = blockIdx.x * 32, n0 = blockIdx.y * 32;
    int tx = threadIdx.x, ty = threadIdx.y;  // 32 x 8
#pragma unroll
    for (int i = 0; i < 4; i++)
        s[ty + i * 8][tx] = W[(size_t)(k0 + ty + i * 8) * N + n0 + tx];
    __syncthreads();
#pragma unroll
    for (int i = 0; i < 4; i++) {
        int n = n0 + ty + i * 8, k = k0 + tx;
        float v = s[tx][ty + i * 8];
        __nv_bfloat16 hi, lo;
        split_bf16(v, hi, lo);
        Oh[(size_t)n * K + k] = hi;
        Ol[(size_t)n * K + k] = lo;
    }
}

// ======================= HMMA GEMM v2: cp.async double buffer + ldmatrix =======================
// 128x128 CTA tile, 8 warps (2 x 4), 64x32 warp tile, KC=16.
// 4 tiles (Ahi,Alo,Bhi,Blo) of [128 rows x 32 B] per stage, 2 stages (32 KB).
// 16B-chunk XOR swizzle (ch ^= (row>>2)&1): STS, cp.async and all ldmatrix
// 8-lane groups are bank-conflict-free (verified by bank walk).
#define KC 16
#define TILE_B 4096
#define STAGE_B (4 * TILE_B)
#define SWZ(row, kb) ((row) * 32 + (((((kb) >> 4) ^ (((row) >> 2) & 1))) << 4) + ((kb) & 15))

template <int MODE>
__global__ void __launch_bounds__(256)
gemm_mm(const float* __restrict__ bias, float* __restrict__ dout) {
    const int Ktot = (MODE == 0 || MODE == 2) ? DD : FF;
    const int CH = Ktot / KC;
    const int e = blockIdx.z;
    const int n0 = blockIdx.x * 128;
    const int m0 = blockIdx.y * 128;

    int cnt = 0, base = 0;
    if (MODE <= 1) {
        cnt = g_counts[e];
        base = g_offsets[e];
        if (m0 >= cnt) return;
    }

    __shared__ __align__(16) char sm[2 * STAGE_B];       // 32 KB
    __shared__ const __nv_bfloat16* ApH[128];
    __shared__ const __nv_bfloat16* ApL[128];

    const int tid = threadIdx.x, wid = tid >> 5, lane = tid & 31;
    const uint32_t sm0 = smem_to_u32(sm);

    const __nv_bfloat16 *Bhi, *Blo;
    const float* bvec;
    if (MODE == 0)      { Bhi = g_We1t_hi + (size_t)e * FF * DD; Blo = g_We1t_lo + (size_t)e * FF * DD; bvec = bias + (size_t)e * FF; }
    else if (MODE == 1) { Bhi = g_We2t_hi + (size_t)e * DD * FF; Blo = g_We2t_lo + (size_t)e * DD * FF; bvec = bias + (size_t)e * DD; }
    else if (MODE == 2) { Bhi = g_Ws1t_hi; Blo = g_Ws1t_lo; bvec = bias; }
    else                { Bhi = g_Ws2t_hi; Blo = g_Ws2t_lo; bvec = bias; }

    for (int r = tid; r < 128; r += 256) {
        int mr = m0 + r;
        const __nv_bfloat16 *ph, *pl;
        if (MODE == 0) {
            int mm = (mr < cnt) ? mr : (cnt - 1);
            int t = g_perm[base + mm];
            ph = g_h_hi + (size_t)t * DD; pl = g_h_lo + (size_t)t * DD;
        } else if (MODE == 1) {
            int mm = (mr < cnt) ? mr : (cnt - 1);
            ph = g_hid_hi + (size_t)(base + mm) * FF; pl = g_hid_lo + (size_t)(base + mm) * FF;
        } else if (MODE == 2) {
            ph = g_h_hi + (size_t)mr * DD; pl = g_h_lo + (size_t)mr * DD;
        } else {
            ph = g_hs_hi + (size_t)mr * FF; pl = g_hs_lo + (size_t)mr * FF;
        }
        ApH[r] = ph; ApL[r] = pl;
    }
    __syncthreads();

    // per-thread cp.async slice: 4 x 16B per chunk
    int ti[4], rr[4], cc[4];
#pragma unroll
    for (int i = 0; i < 4; i++) {
        int u = tid + i * 256;
        ti[i] = u >> 8;
        int w = u & 255;
        rr[i] = w >> 1; cc[i] = w & 1;
    }
    auto load_chunk = [&](int c, int s) {
        const int k0 = c * KC;
        const uint32_t st = sm0 + s * STAGE_B;
#pragma unroll
        for (int i = 0; i < 4; i++) {
            const __nv_bfloat16* src;
            if (ti[i] == 0)      src = ApH[rr[i]] + k0 + cc[i] * 8;
            else if (ti[i] == 1) src = ApL[rr[i]] + k0 + cc[i] * 8;
            else if (ti[i] == 2) src = Bhi + (size_t)(n0 + rr[i]) * Ktot + k0 + cc[i] * 8;
            else                 src = Blo + (size_t)(n0 + rr[i]) * Ktot + k0 + cc[i] * 8;
            cp16(st + ti[i] * TILE_B + rr[i] * 32 + ((cc[i] ^ ((rr[i] >> 2) & 1)) << 4), src);
        }
    };

    const int wm = wid & 1, wn = wid >> 1;
    const int gid = lane >> 2, t2 = lane & 3;
    const int quad = lane >> 3, l8 = lane & 7;

    // ldmatrix lane-offsets (within a tile region)
    uint32_t offA[4], offB[2];
#pragma unroll
    for (int im = 0; im < 4; im++) {
        int row = wm * 64 + im * 16 + l8 + (quad & 1) * 8;
        int ch = quad >> 1;
        offA[im] = (uint32_t)(row * 32 + ((ch ^ ((row >> 2) & 1)) << 4));
    }
#pragma unroll
    for (int p = 0; p < 2; p++) {
        int row = wn * 32 + p * 16 + l8 + ((quad >> 1) & 1) * 8;
        int ch = quad & 1;
        offB[p] = (uint32_t)(row * 32 + ((ch ^ ((row >> 2) & 1)) << 4));
    }

    float acc[4][4][4];
#pragma unroll
    for (int i = 0; i < 4; i++)
#pragma unroll
        for (int j = 0; j < 4; j++)
#pragma unroll
            for (int q = 0; q < 4; q++) acc[i][j][q] = 0.f;

    load_chunk(0, 0);
    CP_COMMIT();

    for (int c = 0; c < CH; c++) {
        if (c + 1 < CH) { load_chunk(c + 1, (c + 1) & 1); CP_COMMIT(); CP_WAIT(1); }
        else            { CP_WAIT(0); }
        __syncthreads();

        const uint32_t st = sm0 + (c & 1) * STAGE_B;
        uint32_t ahi[4][4], alo[4][4], bh[2][4], bl[2][4];
#pragma unroll
        for (int im = 0; im < 4; im++) {
            ldm_x4(st + 0 * TILE_B + offA[im], ahi[im]);
            ldm_x4(st + 1 * TILE_B + offA[im], alo[im]);
        }
#pragma unroll
        for (int p = 0; p < 2; p++) {
            ldm_x4(st + 2 * TILE_B + offB[p], bh[p]);
            ldm_x4(st + 3 * TILE_B + offB[p], bl[p]);
        }
#pragma unroll
        for (int im = 0; im < 4; im++)
#pragma unroll
            for (int nb = 0; nb < 4; nb++) {
                const int p = nb >> 1, j = (nb & 1) * 2;
                mma_bf16(acc[im][nb], ahi[im], bh[p][j], bh[p][j + 1]);
                mma_bf16(acc[im][nb], ahi[im], bl[p][j], bl[p][j + 1]);
                mma_bf16(acc[im][nb], alo[im], bh[p][j], bh[p][j + 1]);
            }
        __syncthreads();
    }

    // ---------------- epilogue ----------------
#pragma unroll
    for (int im = 0; im < 4; im++) {
        const int tr = wm * 64 + im * 16 + gid;
#pragma unroll
        for (int half = 0; half < 2; half++) {
            const int row = tr + half * 8;
            const int mr = m0 + row;
            if (MODE <= 1 && mr >= cnt) continue;
#pragma unroll
            for (int nb = 0; nb < 4; nb++) {
                const int col = n0 + wn * 32 + nb * 8 + t2 * 2;
                float v0 = acc[im][nb][half * 2 + 0] + bvec[col];
                float v1 = acc[im][nb][half * 2 + 1] + bvec[col + 1];
                if (MODE == 0 || MODE == 2) {
                    v0 = gelu_tanh(v0); v1 = gelu_tanh(v1);
                    __nv_bfloat16 h0, l0, h1, l1;
                    split_bf16(v0, h0, l0); split_bf16(v1, h1, l1);
                    uint32_t ph = (uint32_t)__bfloat16_as_ushort(h0) | ((uint32_t)__bfloat16_as_ushort(h1) << 16);
                    uint32_t pl = (uint32_t)__bfloat16_as_ushort(l0) | ((uint32_t)__bfloat16_as_ushort(l1) << 16);
                    size_t rowoff = (MODE == 0) ? (size_t)(base + mr) * FF : (size_t)mr * FF;
                    __nv_bfloat16* dh = (MODE == 0 ? g_hid_hi : g_hs_hi) + rowoff + col;
                    __nv_bfloat16* dl = (MODE == 0 ? g_hid_lo : g_hs_lo) + rowoff + col;
                    *(uint32_t*)dh = ph;
                    *(uint32_t*)dl = pl;
                } else if (MODE == 1) {
                    float w = g_wgt[base + mr];
                    float2* dst = (float2*)(g_partial + (size_t)(base + mr) * DD + col);
                    *dst = make_float2(w * v0, w * v1);
                } else {
                    int p0 = g_posmap[2 * mr], p1 = g_posmap[2 * mr + 1];
                    const float2 r0 = *(const float2*)(g_partial + (size_t)p0 * DD + col);
                    const float2 r1 = *(const float2*)(g_partial + (size_t)p1 * DD + col);
                    float2* dst = (float2*)(dout + (size_t)mr * DD + col);
                    *dst = make_float2(v0 + r0.x + r1.x, v1 + r0.y + r1.y);
                }
            }
        }
    }
}

// ======================= checker: sample-verify all 4 HMMA stages =======================
__global__ void check_kernel(const float* __restrict__ h,
                             const float* __restrict__ We1, const float* __restrict__ be1,
                             const float* __restrict__ We2, const float* __restrict__ be2,
                             const float* __restrict__ Ws1, const float* __restrict__ bs1,
                             const float* __restrict__ Ws2, const float* __restrict__ bs2,
                             const float* __restrict__ out) {
    int gwarp = (blockIdx.x * blockDim.x + threadIdx.x) >> 5;   // 0..511
    int lane = threadIdx.x & 31;
    int stage = gwarp & 3, s = gwarp >> 2;                      // 128 samples/stage

    float ref = 0.f, got = 0.f, acc = 0.f;
    if (stage == 0) {
        int slot = (s * 977 + 13) % SLOTS;
        int e = 0;
        for (int q = 0; q < EE; q++)
            if (slot >= g_offsets[q] && slot < g_offsets[q] + g_counts[q]) e = q;
        int tok = g_perm[slot];
        int n = (s * 613 + 17) % FF;
        for (int k = lane; k < DD; k += 32)
            acc += h[(size_t)tok * DD + k] * We1[(size_t)e * DD * FF + (size_t)k * FF + n];
        for (int o = 16; o > 0; o >>= 1) acc += __shfl_down_sync(0xffffffffu, acc, o);
        ref = gelu_tanh(acc + be1[(size_t)e * FF + n]);
        got = __bfloat162float(g_hid_hi[(size_t)slot * FF + n]) +
              __bfloat162float(g_hid_lo[(size_t)slot * FF + n]);
    } else if (stage == 1) {
        int slot = (s * 769 + 7) % SLOTS;
        int e = 0;
        for (int q = 0; q < EE; q++)
            if (slot >= g_offsets[q] && slot < g_offsets[q] + g_counts[q]) e = q;
        int n = (s * 389 + 5) % DD;
        for (int k = lane; k < FF; k += 32) {
            float a = __bfloat162float(g_hid_hi[(size_t)slot * FF + k]) +
                      __bfloat162float(g_hid_lo[(size_t)slot * FF + k]);
            acc += a * We2[(size_t)e * FF * DD + (size_t)k * DD + n];
        }
        for (int o = 16; o > 0; o >>= 1) acc += __shfl_down_sync(0xffffffffu, acc, o);
        ref = g_wgt[slot] * (acc + be2[(size_t)e * DD + n]);
        got = g_partial[(size_t)slot * DD + n];
    } else if (stage == 2) {
        int m = (s * 137 + 3) % TT;
        int n = (s * 613 + 29) % FF;
        for (int k = lane; k < DD; k += 32)
            acc += h[(size_t)m * DD + k] * Ws1[(size_t)k * FF + n];
        for (int o = 16; o > 0; o >>= 1) acc += __shfl_down_sync(0xffffffffu, acc, o);
        ref = gelu_tanh(acc + bs1[n]);
        got = __bfloat162float(g_hs_hi[(size_t)m * FF + n]) +
              __bfloat162float(g_hs_lo[(size_t)m * FF + n]);
    } else {
        int m = (s * 541 + 11) % TT;
        int n = (s * 257 + 19) % DD;
        for (int k = lane; k < FF; k += 32) {
            float a = __bfloat162float(g_hs_hi[(size_t)m * FF + k]) +
                      __bfloat162float(g_hs_lo[(size_t)m * FF + k]);
            acc += a * Ws2[(size_t)k * DD + n];
        }
        for (int o = 16; o > 0; o >>= 1) acc += __shfl_down_sync(0xffffffffu, acc, o);
        if (lane == 0) {
            int p0 = g_posmap[2 * m], p1 = g_posmap[2 * m + 1];
            ref = acc + bs2[n] + g_partial[(size_t)p0 * DD + n] + g_partial[(size_t)p1 * DD + n];
            got = out[(size_t)m * DD + n];
        }
    }
    if (lane == 0) {
        float d = fabsf(ref - got);
        if (!(d <= 1e-2f * fmaxf(1.f, fabsf(ref)))) g_fail = 1;   // NaN-safe: NaN fails
    }
}

// ======================= FFMA fallback GEMM (R1, proven) =======================
template <int MODE>
__global__ void __launch_bounds__(256, 2)
gemm_tile(const float* __restrict__ Aext, const float* __restrict__ W,
          const float* __restrict__ bias, float* __restrict__ dout) {
    if (g_fail == 0) return;    // HMMA verified good -> skip
    const int Kd = (MODE == 0 || MODE == 2) ? DD : FF;
    const int Nd = (MODE == 0 || MODE == 2) ? FF : DD;
    const int e  = blockIdx.z;
    const int n0 = blockIdx.x * 128;
    const int m0 = blockIdx.y * 128;

    int cnt = 0, base = 0;
    if (MODE <= 1) {
        cnt = g_counts[e];
        base = g_offsets[e];
        if (m0 >= cnt) return;
    }

    const float* Bmat;
    const float* bvec;
    if (MODE == 0)      { Bmat = W + (size_t)e * DD * FF; bvec = bias + (size_t)e * FF; }
    else if (MODE == 1) { Bmat = W + (size_t)e * FF * DD; bvec = bias + (size_t)e * DD; }
    else                { Bmat = W; bvec = bias; }

    __shared__ float As[8][128];
    __shared__ float Bs[8][128];
    __shared__ const float* Ap[128];

    const int tid = threadIdx.x;
    for (int r = tid; r < 128; r += 256) {
        int mr = m0 + r;
        const float* p;
        if (MODE == 0) {
            int mm = (mr < cnt) ? mr : (cnt - 1);
            p = Aext + (size_t)g_perm[base + mm] * DD;
        } else if (MODE == 1) {
            int mm = (mr < cnt) ? mr : (cnt - 1);
            p = g_hid + (size_t)(base + mm) * FF;
        } else if (MODE == 2) {
            p = Aext + (size_t)mr * DD;
        } else {
            p = g_hid_s + (size_t)mr * FF;
        }
        Ap[r] = p;
    }
    __syncthreads();

    const int tx = tid & 15, ty = tid >> 4;
    const int aRow = tid >> 1, aCol = (tid & 1) * 4;
    const int bRow = tid >> 5, bCol = (tid & 31) * 4;

    float c[8][8];
#pragma unroll
    for (int i = 0; i < 8; i++)
#pragma unroll
        for (int j = 0; j < 8; j++) c[i][j] = 0.f;

    for (int kt = 0; kt < Kd; kt += 8) {
        float4 av = *(const float4*)(Ap[aRow] + kt + aCol);
        As[aCol + 0][aRow] = av.x;
        As[aCol + 1][aRow] = av.y;
        As[aCol + 2][aRow] = av.z;
        As[aCol + 3][aRow] = av.w;
        float4 bv = *(const float4*)(Bmat + (size_t)(kt + bRow) * Nd + n0 + bCol);
        *(float4*)&Bs[bRow][bCol] = bv;
        __syncthreads();
#pragma unroll
        for (int k = 0; k < 8; k++) {
            float4 a0 = *(float4*)&As[k][ty * 8];
            float4 a1 = *(float4*)&As[k][ty * 8 + 4];
            float4 b0 = *(float4*)&Bs[k][tx * 8];
            float4 b1 = *(float4*)&Bs[k][tx * 8 + 4];
            float ra[8] = {a0.x, a0.y, a0.z, a0.w, a1.x, a1.y, a1.z, a1.w};
            float rb[8] = {b0.x, b0.y, b0.z, b0.w, b1.x, b1.y, b1.z, b1.w};
#pragma unroll
            for (int i = 0; i < 8; i++)
#pragma unroll
                for (int j = 0; j < 8; j++) c[i][j] = fmaf(ra[i], rb[j], c[i][j]);
        }
        __syncthreads();
    }

#pragma unroll
    for (int i = 0; i < 8; i++) {
        int mr = m0 + ty * 8 + i;
        if (MODE <= 1 && mr >= cnt) continue;
        if (MODE == 0) {
            float* crow = g_hid + (size_t)(base + mr) * FF;
#pragma unroll
            for (int j = 0; j < 8; j++) {
                int n = n0 + tx * 8 + j;
                crow[n] = gelu_tanh(c[i][j] + bvec[n]);
            }
        } else if (MODE == 1) {
            float w = g_wgt[base + mr];
            float* crow = g_partial + (size_t)(base + mr) * DD;
#pragma unroll
            for (int j = 0; j < 8; j++) {
                int n = n0 + tx * 8 + j;
                crow[n] = w * (c[i][j] + bvec[n]);
            }
        } else if (MODE == 2) {
            float* crow = g_hid_s + (size_t)mr * FF;
#pragma unroll
            for (int j = 0; j < 8; j++) {
                int n = n0 + tx * 8 + j;
                crow[n] = gelu_tanh(c[i][j] + bvec[n]);
            }
        } else {
            int p0 = g_posmap[2 * mr], p1 = g_posmap[2 * mr + 1];
            const float* r0 = g_partial + (size_t)p0 * DD;
            const float* r1 = g_partial + (size_t)p1 * DD;
            float* crow = dout + (size_t)mr * DD;
#pragma unroll
            for (int j = 0; j < 8; j++) {
                int n = n0 + tx * 8 + j;
                crow[n] = c[i][j] + bvec[n] + r0[n] + r1[n];
            }
        }
    }
}

// ======================= launch =======================
extern "C" void kernel_launch(void* const* d_in, const int* in_sizes, int n_in,
                              void* d_out, int out_size) {
    const float* h   = (const float*)d_in[0];
    const float* Wr  = (const float*)d_in[1];
    const float* br  = (const float*)d_in[2];
    const float* We1 = (const float*)d_in[3];
    const float* be1 = (const float*)d_in[4];
    const float* We2 = (const float*)d_in[5];
    const float* be2 = (const float*)d_in[6];
    const float* Ws1 = (const float*)d_in[7];
    const float* bs1 = (const float*)d_in[8];
    const float* Ws2 = (const float*)d_in[9];
    const float* bs2 = (const float*)d_in[10];
    float* out = (float*)d_out;

    init_kernel<<<1, 32>>>(out, out_size);
    router_kernel<<<TT / 8, 256>>>(h, Wr, br);
    scan_kernel<<<1, 32>>>();
    scatter_kernel<<<TT / 256, 256>>>();

    // ---- HMMA path: only harness pointers cross the launch boundary ----
    conv_h_kernel<<<(TT * DD / 4 + 255) / 256, 256>>>(h);
    transpose_split<0><<<dim3(DD / 32, FF / 32, EE), dim3(32, 8)>>>(We1);
    transpose_split<1><<<dim3(FF / 32, DD / 32, EE), dim3(32, 8)>>>(We2);
    transpose_split<2><<<dim3(DD / 32, FF / 32, 1), dim3(32, 8)>>>(Ws1);
    transpose_split<3><<<dim3(FF / 32, DD / 32, 1), dim3(32, 8)>>>(Ws2);
    gemm_mm<0><<<dim3(FF / 128, TT / 128, EE), 256>>>(be1, nullptr);
    gemm_mm<1><<<dim3(DD / 128, TT / 128, EE), 256>>>(be2, nullptr);
    gemm_mm<2><<<dim3(FF / 128, TT / 128, 1), 256>>>(bs1, nullptr);
    gemm_mm<3><<<dim3(DD / 128, TT / 128, 1), 256>>>(bs2, out);

    // ---- verify HMMA result on 512 samples ----
    check_kernel<<<64, 256>>>(h, We1, be1, We2, be2, Ws1, bs1, Ws2, bs2, out);

    // ---- FFMA fallback (early-exits when HMMA verified) ----
    gemm_tile<0><<<dim3(FF / 128, TT / 128, EE), 256>>>(h, We1, be1, nullptr);
    gemm_tile<1><<<dim3(DD / 128, TT / 128, EE), 256>>>(nullptr, We2, be2, nullptr);
    gemm_tile<2><<<dim3(FF / 128, TT / 128, 1), 256>>>(h, Ws1, bs1, nullptr);
    gemm_tile<3><<<dim3(DD / 128, TT / 128, 1), 256>>>(nullptr, Ws2, bs2, out);
}